// round 3
// baseline (speedup 1.0000x reference)
#include <cuda_runtime.h>
#include <cstdint>

#define N_ROWS 65536
#define DIM    256
#define K_CODES 1024

// ---------------- scratch (no allocations allowed) ----------------
__device__ float g_eT[K_CODES * DIM];   // transposed codebook [k][d]
__device__ float g_b[K_CODES];          // ||e_k||^2
__device__ int   g_idx[N_ROWS];         // argmin indices
__device__ int   g_hist[K_CODES];       // codebook usage histogram
__device__ float g_part[N_ROWS / 8];    // per-block loss partials

// ---------------- kernel 0: transpose e, ||e_k||^2, zero hist ----------------
__global__ void __launch_bounds__(256) prep_kernel(const float* __restrict__ e) {
    int k = blockIdx.x;       // 0..1023
    int d = threadIdx.x;      // 0..255
    float v = e[(size_t)d * K_CODES + k];
    g_eT[k * DIM + d] = v;

    __shared__ float red[256];
    red[d] = __fmul_rn(v, v);
    __syncthreads();
    #pragma unroll
    for (int off = 128; off > 0; off >>= 1) {
        if (d < off) red[d] = __fadd_rn(red[d], red[d + off]);
        __syncthreads();
    }
    if (d == 0) g_b[k] = red[0];
    if (blockIdx.x < 4) g_hist[blockIdx.x * 256 + d] = 0;
}

// ---------------- kernel 1: fused distance GEMM + argmin ----------------
// Block: 32 rows, 256 threads. Each thread handles code k = kk*256+tid for
// kk=0..3 (ascending -> low-index tie break preserved), accumulating 32 row
// dots as 16 packed f32x2 registers. Distance replicates the reference op
// structure exactly: fl(fl(a + b) - 2*m), no FMA contraction in the epilogue.
__global__ void __launch_bounds__(256, 2) argmin_kernel(const float* __restrict__ z,
                                                        const float* __restrict__ e) {
    __shared__ __align__(8) float z2[DIM][34];   // [d][row], pad 34: conflict-free, 8B-aligned rows
    __shared__ float a_s[32];                    // ||z_row||^2
    __shared__ unsigned long long key[32];       // (dist_bits<<32)|k  running min

    int tid = threadIdx.x;
    size_t base = (size_t)blockIdx.x * 32;
    const float* zrow = z + base * DIM;

    for (int i = tid; i < 32 * DIM; i += 256) {
        int d = i & (DIM - 1);
        int r = i >> 8;
        z2[d][r] = zrow[i];
    }
    if (tid < 32) key[tid] = ~0ull;
    __syncthreads();

    if (tid < 32) {
        // square-then-add, sequential d (mimic jnp.sum(z**2) structure)
        float s = 0.f;
        for (int d = 0; d < DIM; d++) {
            float v = z2[d][tid];
            s = __fadd_rn(s, __fmul_rn(v, v));
        }
        a_s[tid] = s;
    }
    __syncthreads();

    for (int kk = 0; kk < 4; kk++) {
        int k = kk * 256 + tid;
        float bk = g_b[k];

        unsigned long long acc[16];
        #pragma unroll
        for (int j = 0; j < 16; j++) acc[j] = 0ull;   // (0.f, 0.f)

        const float* ecol = e + k;
        #pragma unroll 4
        for (int d = 0; d < DIM; d++) {
            float ev = __ldg(ecol + (size_t)d * K_CODES);
            unsigned long long evv;
            asm("mov.b64 %0, {%1, %1};" : "=l"(evv) : "f"(ev));
            const unsigned long long* zp =
                reinterpret_cast<const unsigned long long*>(&z2[d][0]);
            #pragma unroll
            for (int j = 0; j < 16; j++) {
                unsigned long long zv = zp[j];   // rows (2j, 2j+1), broadcast LDS.64
                asm("fma.rn.f32x2 %0, %1, %2, %0;"
                    : "+l"(acc[j]) : "l"(zv), "l"(evv));
            }
        }

        #pragma unroll
        for (int j = 0; j < 16; j++) {
            float m0, m1;
            asm("mov.b64 {%0, %1}, %2;" : "=f"(m0), "=f"(m1) : "l"(acc[j]));
            float d0 = __fsub_rn(__fadd_rn(a_s[2 * j],     bk), 2.0f * m0);
            float d1 = __fsub_rn(__fadd_rn(a_s[2 * j + 1], bk), 2.0f * m1);
            unsigned long long c0 =
                ((unsigned long long)__float_as_uint(d0) << 32) | (unsigned)k;
            unsigned long long c1 =
                ((unsigned long long)__float_as_uint(d1) << 32) | (unsigned)k;
            atomicMin(&key[2 * j],     c0);
            atomicMin(&key[2 * j + 1], c1);
        }
    }
    __syncthreads();

    if (tid < 32) {
        g_idx[base + tid] = (int)(key[tid] & 0xFFFFFFFFull);
    }
}

// ---------------- kernel 2: gather + straight-through + loss partials + hist ----------------
__global__ void __launch_bounds__(256) gather_kernel(const float* __restrict__ z,
                                                     float* __restrict__ out_q,
                                                     float* __restrict__ out_if,
                                                     int write_q, int write_i) {
    int tid = threadIdx.x;
    int warp = tid >> 5, lane = tid & 31;
    size_t row = (size_t)blockIdx.x * 8 + warp;
    int k = g_idx[row];
    const float* zr = z + row * DIM;
    const float* er = g_eT + (size_t)k * DIM;

    float sq = 0.f;
    #pragma unroll
    for (int j = 0; j < 8; j++) {
        int d = lane + 32 * j;
        float zv = zr[d];
        float qv = er[d];
        float df = __fsub_rn(qv, zv);
        if (write_q) out_q[row * DIM + d] = __fadd_rn(zv, df);  // z + (q - z), exact replication
        sq = __fadd_rn(sq, __fmul_rn(df, df));
    }
    #pragma unroll
    for (int o = 16; o > 0; o >>= 1)
        sq = __fadd_rn(sq, __shfl_down_sync(0xffffffffu, sq, o));

    __shared__ float ws[8];
    if (lane == 0) {
        ws[warp] = sq;
        atomicAdd(&g_hist[k], 1);
        if (write_i) out_if[row] = (float)k;
    }
    __syncthreads();
    if (tid == 0) {
        float s = 0.f;
        #pragma unroll
        for (int w = 0; w < 8; w++) s = __fadd_rn(s, ws[w]);
        g_part[blockIdx.x] = s;
    }
}

// ---------------- kernel 3: deterministic final reductions ----------------
__global__ void __launch_bounds__(256) final_kernel(float* __restrict__ out_s, int write_s) {
    __shared__ float red[256];
    int tid = threadIdx.x;

    float s = 0.f;
    for (int i = tid; i < N_ROWS / 8; i += 256) s = __fadd_rn(s, g_part[i]);
    red[tid] = s;
    __syncthreads();
    #pragma unroll
    for (int off = 128; off > 0; off >>= 1) {
        if (tid < off) red[tid] = __fadd_rn(red[tid], red[tid + off]);
        __syncthreads();
    }
    float vq = red[0] / 16777216.0f;
    __syncthreads();

    float ps = 0.f;
    for (int i = tid; i < K_CODES; i += 256) {
        float p = (float)g_hist[i] * (1.0f / 65536.0f);
        ps = __fadd_rn(ps, __fmul_rn(p, logf(p + 1e-10f)));
    }
    red[tid] = ps;
    __syncthreads();
    #pragma unroll
    for (int off = 128; off > 0; off >>= 1) {
        if (tid < off) red[tid] = __fadd_rn(red[tid], red[tid + off]);
        __syncthreads();
    }
    if (tid == 0 && write_s) {
        out_s[0] = vq;               // vq_loss
        out_s[1] = 0.25f * vq;       // commitment_loss (beta * same mean)
        out_s[2] = expf(-red[0]);    // perplexity
    }
}

// ---------------- launch ----------------
extern "C" void kernel_launch(void* const* d_in, const int* in_sizes, int n_in,
                              void* d_out, int out_size) {
    const float* z = (const float*)d_in[0];
    const float* e = (const float*)d_in[1];
    float* out = (float*)d_out;

    const int QN = N_ROWS * DIM;  // 16777216
    int write_q = (out_size >= QN) ? 1 : 0;
    int write_i = (out_size >= QN + N_ROWS) ? 1 : 0;
    int write_s = 0;
    float* out_q  = out;
    float* out_if = out + QN;
    float* out_s  = out;
    if (out_size >= QN + N_ROWS + 3) {          // full tuple: q | idx | 3 scalars
        write_s = 1; out_s = out + QN + N_ROWS;
    } else if (out_size == QN + 3) {            // q | 3 scalars
        write_s = 1; out_s = out + QN; write_i = 0;
    }

    prep_kernel<<<K_CODES, 256>>>(e);
    argmin_kernel<<<N_ROWS / 32, 256>>>(z, e);
    gather_kernel<<<N_ROWS / 8, 256>>>(z, out_q, out_if, write_q, write_i);
    final_kernel<<<1, 256>>>(out_s, write_s);
}

// round 8
// speedup vs baseline: 1.5516x; 1.5516x over previous
#include <cuda_runtime.h>
#include <cstdint>

#define N_ROWS 65536
#define DIM    256
#define K_CODES 1024
#define MARGIN 2e-4f

// ================= scratch (no allocations allowed) =================
__device__ uint32_t g_Ah[N_ROWS * DIM];   // z tf32 plane, A-fragment-linearized
__device__ uint32_t g_Bh[K_CODES * DIM];  // e tf32 plane, B-fragment-linearized
__device__ float g_eT[K_CODES * DIM];     // transposed codebook [k][d]
__device__ float g_a[N_ROWS];             // ||z_row||^2 (exact replication)
__device__ float g_b[K_CODES];            // ||e_k||^2
__device__ int   g_idx[N_ROWS];
__device__ int   g_hist[K_CODES];
__device__ float g_part[N_ROWS / 8];

// ================= helpers =================
__device__ __forceinline__ uint32_t smem_u32(const void* p) {
    uint32_t a;
    asm("{ .reg .u64 t; cvta.to.shared.u64 t, %1; cvt.u32.u64 %0, t; }" : "=r"(a) : "l"(p));
    return a;
}
__device__ __forceinline__ void cp16(uint32_t dst, const void* src) {
    asm volatile("cp.async.cg.shared.global [%0], [%1], 16;" :: "r"(dst), "l"(src));
}
__device__ __forceinline__ uint32_t f2tf32(float v) {
    uint32_t r;
    asm("cvt.rna.tf32.f32 %0, %1;" : "=r"(r) : "f"(v));
    return r;
}
__device__ __forceinline__ void mma8(float* c, const uint4& a, const uint2& b) {
    asm("mma.sync.aligned.m16n8k8.row.col.f32.tf32.tf32.f32 "
        "{%0,%1,%2,%3}, {%4,%5,%6,%7}, {%8,%9}, {%0,%1,%2,%3};"
        : "+f"(c[0]), "+f"(c[1]), "+f"(c[2]), "+f"(c[3])
        : "r"(a.x), "r"(a.y), "r"(a.z), "r"(a.w), "r"(b.x), "r"(b.y));
}
__device__ __forceinline__ uint32_t fmap(float f) {
    uint32_t u = __float_as_uint(f);
    return (u >> 31) ? ~u : (u | 0x80000000u);
}
__device__ __forceinline__ float funmap(uint32_t u) {
    return __uint_as_float((u >> 31) ? (u & 0x7fffffffu) : ~u);
}

// ---------- prepass A: z -> tf32 plane (A-fragment order) + exact ||z||^2 ----------
// A frag (m16n8k8): a0=(g,q) a1=(g+8,q) a2=(g,q+4) a3=(g+8,q+4), g=lane>>2, q=lane&3
// plane layout: tile t = (row/16)*32 + (k/8); elem = t*128 + lane*4 + j
__global__ void __launch_bounds__(256) prepA_kernel(const float* __restrict__ z) {
    __shared__ float zs[32 * 260];
    int tid = threadIdx.x;
    const float4* src = reinterpret_cast<const float4*>(z + (size_t)blockIdx.x * 32 * DIM);
    #pragma unroll
    for (int i = 0; i < 8; i++) {
        int gi = tid + i * 256;
        int row = gi >> 6, c4 = gi & 63;
        *reinterpret_cast<float4*>(&zs[row * 260 + c4 * 4]) = src[gi];
    }
    __syncthreads();
    uint32_t outbase = blockIdx.x * 8192;
    #pragma unroll
    for (int i = 0; i < 8; i++) {
        int o = (tid + i * 256) * 4;
        int rt_local = o >> 12;
        int rem = o & 4095;
        int kt = rem >> 7;
        int lane = (rem >> 2) & 31;
        int g = lane >> 2, q = lane & 3;
        uint32_t h4[4];
        #pragma unroll
        for (int j = 0; j < 4; j++) {
            int row = rt_local * 16 + g + (j & 1) * 8;
            int col = kt * 8 + q + ((j >> 1) & 1) * 4;
            h4[j] = f2tf32(zs[row * 260 + col]);
        }
        *reinterpret_cast<uint4*>(&g_Ah[outbase + o]) = make_uint4(h4[0], h4[1], h4[2], h4[3]);
    }
    if (tid < 32) {   // exact sequential square-then-add (replicates reference)
        float s = 0.f;
        for (int d = 0; d < DIM; d++) {
            float v = zs[tid * 260 + d];
            s = __fadd_rn(s, __fmul_rn(v, v));
        }
        g_a[(size_t)blockIdx.x * 32 + tid] = s;
    }
}

// ---------- prepass B: e^T, ||e_k||^2, tf32 plane (B-frag order), hist zero ----------
// B frag (col): b0=(k=q,n=g) b1=(k=q+4,n=g); tile t=(code/8)*32+(d/8); elem=t*64+lane*2+hi4
__global__ void __launch_bounds__(256) prepB_kernel(const float* __restrict__ e) {
    int k = blockIdx.x;       // code 0..1023
    int d = threadIdx.x;      // dim  0..255
    float v = e[(size_t)d * K_CODES + k];
    g_eT[k * DIM + d] = v;

    __shared__ float red[256];
    red[d] = __fmul_rn(v, v);
    __syncthreads();
    #pragma unroll
    for (int off = 128; off > 0; off >>= 1) {
        if (d < off) red[d] = __fadd_rn(red[d], red[d + off]);
        __syncthreads();
    }
    if (d == 0) g_b[k] = red[0];
    if (blockIdx.x < 4) g_hist[blockIdx.x * 256 + d] = 0;

    int q = d & 3, hi4 = (d >> 2) & 1, g = k & 7;
    int lane = g * 4 + q;
    int idx = ((k >> 3) * 32 + (d >> 3)) * 64 + lane * 2 + hi4;
    g_Bh[idx] = f2tf32(v);
}

// ---------- main GEMM (tf32) + candidate shortlist + exact refine ----------
// CTA: 128 rows x all 1024 codes. 8 warps (4M x 2N), warp tile 32x64.
// smem floats: A[32768] | B 2 stages x 4096 @32768 | b_s[1024]@40960 |
//              row_min[128]@41984 | cnt[128]@42112 | cand[128*32]@42240  -> 46336 fl
#define SM_B    32768
#define SM_BS   40960
#define SM_RMIN 41984
#define SM_CNT  42112
#define SM_CAND 42240
#define GEMM_SMEM_BYTES (46336 * 4)

__global__ void __launch_bounds__(256) gemm_argmin_kernel(const float* __restrict__ z) {
    extern __shared__ __align__(16) float s[];
    int tid = threadIdx.x, lane = tid & 31, wid = tid >> 5;
    int warp_m = wid & 3, warp_n = wid >> 2;
    int rblk = blockIdx.x;
    float* b_s = s + SM_BS;
    uint32_t* row_min = reinterpret_cast<uint32_t*>(s + SM_RMIN);
    int* cnt = reinterpret_cast<int*>(s + SM_CNT);
    uint32_t* cand = reinterpret_cast<uint32_t*>(s + SM_CAND);
    uint32_t sbase = smem_u32(s);

    // init scalars
    #pragma unroll
    for (int i = 0; i < 4; i++) b_s[tid + i * 256] = g_b[tid + i * 256];
    if (tid < 128) { row_min[tid] = 0xFFFFFFFFu; cnt[tid] = 0; }

    // A resident load (128 rows x 256 dims, frag-linearized = contiguous slice)
    {
        const uint32_t* srcA = g_Ah + (size_t)rblk * 32768;
        #pragma unroll
        for (int i = 0; i < 32; i++) {
            int f = tid + i * 256;               // float4 id 0..8191
            cp16(sbase + (uint32_t)f * 16, srcA + (size_t)f * 4);
        }
    }
    // B chunk loader: i -> (nb = i>>3, c = i&7), stage i&1
    auto loadB = [&](int i) {
        int nb = i >> 3, c = i & 7, st = i & 1;
        #pragma unroll
        for (int it = 0; it < 4; it++) {
            int f = tid + it * 256;              // float4 id 0..1023
            int nt = f >> 6, w = f & 63;
            const uint32_t* src = g_Bh + ((size_t)((nb * 16 + nt) * 32 + c * 4)) * 64 + w * 4;
            cp16(sbase + (uint32_t)(SM_B + st * 4096 + nt * 256 + w * 4) * 4, src);
        }
        asm volatile("cp.async.commit_group;" ::: "memory");
    };
    loadB(0);                                    // group 0 (includes A cp's)
    loadB(1);                                    // group 1

    float acc[2][8][4];
    int g = lane >> 2, q2 = (lane & 3) * 2;

    for (int i = 0; i < 64; i++) {
        int nb = i >> 3, c = i & 7, st = i & 1;
        if (i < 63) asm volatile("cp.async.wait_group 1;" ::: "memory");
        else        asm volatile("cp.async.wait_group 0;" ::: "memory");
        __syncthreads();

        if (c == 0) {
            #pragma unroll
            for (int m = 0; m < 2; m++)
                #pragma unroll
                for (int n = 0; n < 8; n++)
                    #pragma unroll
                    for (int j = 0; j < 4; j++) acc[m][n][j] = 0.f;
        }

        const float* Bs = s + SM_B + st * 4096;
        #pragma unroll
        for (int kt = 0; kt < 4; kt++) {
            uint4 ah[2];
            #pragma unroll
            for (int m = 0; m < 2; m++)
                ah[m] = *reinterpret_cast<const uint4*>(
                    &s[(warp_m * 2 + m) * 4096 + (c * 4 + kt) * 128 + lane * 4]);
            uint2 bh[8];
            #pragma unroll
            for (int n = 0; n < 8; n++)
                bh[n] = *reinterpret_cast<const uint2*>(
                    &Bs[(warp_n * 8 + n) * 256 + kt * 64 + lane * 2]);
            #pragma unroll
            for (int m = 0; m < 2; m++)
                #pragma unroll
                for (int n = 0; n < 8; n++) mma8(acc[m][n], ah[m], bh[n]);
        }

        if (c == 7) {
            // phase 1: per-row running min (selection metric d = b - 2m, no a)
            #pragma unroll
            for (int m = 0; m < 2; m++) {
                float mn0 = __int_as_float(0x7f800000), mn1 = mn0;
                #pragma unroll
                for (int n = 0; n < 8; n++) {
                    int nl = warp_n * 64 + n * 8 + q2;
                    float b0 = b_s[nb * 128 + nl], b1 = b_s[nb * 128 + nl + 1];
                    mn0 = fminf(mn0, fminf(__fmaf_rn(-2.f, acc[m][n][0], b0),
                                           __fmaf_rn(-2.f, acc[m][n][1], b1)));
                    mn1 = fminf(mn1, fminf(__fmaf_rn(-2.f, acc[m][n][2], b0),
                                           __fmaf_rn(-2.f, acc[m][n][3], b1)));
                }
                #pragma unroll
                for (int off = 1; off <= 2; off <<= 1) {
                    mn0 = fminf(mn0, __shfl_xor_sync(0xffffffffu, mn0, off));
                    mn1 = fminf(mn1, __shfl_xor_sync(0xffffffffu, mn1, off));
                }
                if ((lane & 3) == 0) {
                    int r0 = warp_m * 32 + m * 16 + g;
                    atomicMin(&row_min[r0], fmap(mn0));
                    atomicMin(&row_min[r0 + 8], fmap(mn1));
                }
            }
            __syncthreads();
            // phase 2: collect candidates within margin of running min
            #pragma unroll
            for (int m = 0; m < 2; m++) {
                int r0 = warp_m * 32 + m * 16 + g, r1 = r0 + 8;
                float t0 = funmap(row_min[r0]) + MARGIN;
                float t1 = funmap(row_min[r1]) + MARGIN;
                #pragma unroll
                for (int n = 0; n < 8; n++) {
                    int nl = warp_n * 64 + n * 8 + q2;
                    float b0 = b_s[nb * 128 + nl], b1 = b_s[nb * 128 + nl + 1];
                    unsigned code = (unsigned)(nb * 128 + nl);
                    float d00 = __fmaf_rn(-2.f, acc[m][n][0], b0);
                    float d01 = __fmaf_rn(-2.f, acc[m][n][1], b1);
                    float d10 = __fmaf_rn(-2.f, acc[m][n][2], b0);
                    float d11 = __fmaf_rn(-2.f, acc[m][n][3], b1);
                    if (d00 <= t0) { int p = atomicAdd(&cnt[r0], 1); if (p < 32) cand[r0 * 32 + p] = code; }
                    if (d01 <= t0) { int p = atomicAdd(&cnt[r0], 1); if (p < 32) cand[r0 * 32 + p] = code + 1; }
                    if (d10 <= t1) { int p = atomicAdd(&cnt[r1], 1); if (p < 32) cand[r1 * 32 + p] = code; }
                    if (d11 <= t1) { int p = atomicAdd(&cnt[r1], 1); if (p < 32) cand[r1 * 32 + p] = code + 1; }
                }
            }
        }
        __syncthreads();
        if (i + 2 < 64) loadB(i + 2);
    }

    // ---- exact refine: R2-identical numerics (sequential FMA, fl(fl(a+b)-2m)) ----
    if (tid < 128) {
        int row = rblk * 128 + tid;
        float a = g_a[row];
        int nc = cnt[tid]; if (nc > 32) nc = 32;
        const float* zr = z + (size_t)row * DIM;
        unsigned long long best = ~0ull;
        for (int ci = 0; ci < nc; ci++) {
            int k = (int)cand[tid * 32 + ci];
            const float* er = g_eT + (size_t)k * DIM;
            float m = 0.f;
            for (int d = 0; d < DIM; d++) m = __fmaf_rn(zr[d], er[d], m);
            float dist = __fsub_rn(__fadd_rn(a, b_s[k]), 2.0f * m);
            unsigned long long key =
                ((unsigned long long)__float_as_uint(dist) << 32) | (unsigned)k;
            if (key < best) best = key;
        }
        g_idx[row] = (int)(best & 0xFFFFFFFFull);
    }
}

// ---------------- gather + straight-through + loss partials + hist ----------------
__global__ void __launch_bounds__(256) gather_kernel(const float* __restrict__ z,
                                                     float* __restrict__ out_q,
                                                     float* __restrict__ out_if,
                                                     int write_q, int write_i) {
    int tid = threadIdx.x;
    int warp = tid >> 5, lane = tid & 31;
    size_t row = (size_t)blockIdx.x * 8 + warp;
    int k = g_idx[row];
    const float* zr = z + row * DIM;
    const float* er = g_eT + (size_t)k * DIM;

    float sq = 0.f;
    #pragma unroll
    for (int j = 0; j < 8; j++) {
        int d = lane + 32 * j;
        float zv = zr[d];
        float qv = er[d];
        float df = __fsub_rn(qv, zv);
        if (write_q) out_q[row * DIM + d] = __fadd_rn(zv, df);
        sq = __fadd_rn(sq, __fmul_rn(df, df));
    }
    #pragma unroll
    for (int o = 16; o > 0; o >>= 1)
        sq = __fadd_rn(sq, __shfl_down_sync(0xffffffffu, sq, o));

    __shared__ float ws[8];
    if (lane == 0) {
        ws[warp] = sq;
        atomicAdd(&g_hist[k], 1);
        if (write_i) out_if[row] = (float)k;
    }
    __syncthreads();
    if (tid == 0) {
        float s = 0.f;
        #pragma unroll
        for (int w = 0; w < 8; w++) s = __fadd_rn(s, ws[w]);
        g_part[blockIdx.x] = s;
    }
}

// ---------------- final reductions ----------------
__global__ void __launch_bounds__(256) final_kernel(float* __restrict__ out_s, int write_s) {
    __shared__ float red[256];
    int tid = threadIdx.x;

    float s = 0.f;
    for (int i = tid; i < N_ROWS / 8; i += 256) s = __fadd_rn(s, g_part[i]);
    red[tid] = s;
    __syncthreads();
    #pragma unroll
    for (int off = 128; off > 0; off >>= 1) {
        if (tid < off) red[tid] = __fadd_rn(red[tid], red[tid + off]);
        __syncthreads();
    }
    float vq = red[0] / 16777216.0f;
    __syncthreads();

    float ps = 0.f;
    for (int i = tid; i < K_CODES; i += 256) {
        float p = (float)g_hist[i] * (1.0f / 65536.0f);
        ps = __fadd_rn(ps, __fmul_rn(p, logf(p + 1e-10f)));
    }
    red[tid] = ps;
    __syncthreads();
    #pragma unroll
    for (int off = 128; off > 0; off >>= 1) {
        if (tid < off) red[tid] = __fadd_rn(red[tid], red[tid + off]);
        __syncthreads();
    }
    if (tid == 0 && write_s) {
        out_s[0] = vq;
        out_s[1] = 0.25f * vq;
        out_s[2] = expf(-red[0]);
    }
}

// ---------------- launch ----------------
extern "C" void kernel_launch(void* const* d_in, const int* in_sizes, int n_in,
                              void* d_out, int out_size) {
    const float* z = (const float*)d_in[0];
    const float* e = (const float*)d_in[1];
    float* out = (float*)d_out;

    const int QN = N_ROWS * DIM;
    int write_q = (out_size >= QN) ? 1 : 0;
    int write_i = (out_size >= QN + N_ROWS) ? 1 : 0;
    int write_s = 0;
    float* out_q  = out;
    float* out_if = out + QN;
    float* out_s  = out;
    if (out_size >= QN + N_ROWS + 3) {
        write_s = 1; out_s = out + QN + N_ROWS;
    } else if (out_size == QN + 3) {
        write_s = 1; out_s = out + QN; write_i = 0;
    }

    cudaFuncSetAttribute(gemm_argmin_kernel,
                         cudaFuncAttributeMaxDynamicSharedMemorySize, GEMM_SMEM_BYTES);

    prepA_kernel<<<N_ROWS / 32, 256>>>(z);
    prepB_kernel<<<K_CODES, 256>>>(e);
    gemm_argmin_kernel<<<N_ROWS / 128, 256, GEMM_SMEM_BYTES>>>(z);
    gather_kernel<<<N_ROWS / 8, 256>>>(z, out_q, out_if, write_q, write_i);
    final_kernel<<<1, 256>>>(out_s, write_s);
}

// round 12
// speedup vs baseline: 1.8682x; 1.2040x over previous
#include <cuda_runtime.h>
#include <cstdint>

#define N_ROWS 65536
#define DIM    256
#define K_CODES 1024
#define MARGIN 2.5e-4f

// ================= scratch (no allocations allowed) =================
__device__ uint4 g_A4[N_ROWS * 32];              // z fp16 plane, A-frag-linearized (8 f16/uint4)
__device__ unsigned short g_B16[K_CODES * DIM];  // e fp16 plane, B-frag-linearized
__device__ float g_eT[K_CODES * DIM];            // transposed codebook [k][d]
__device__ float g_a[N_ROWS];                    // ||z_row||^2 (exact replication)
__device__ float g_b[K_CODES];                   // ||e_k||^2
__device__ int   g_idx[N_ROWS];
__device__ int   g_hist[K_CODES];
__device__ float g_part[N_ROWS / 8];

// ================= helpers =================
__device__ __forceinline__ uint32_t smem_u32(const void* p) {
    uint32_t a;
    asm("{ .reg .u64 t; cvta.to.shared.u64 t, %1; cvt.u32.u64 %0, t; }" : "=r"(a) : "l"(p));
    return a;
}
__device__ __forceinline__ void cp16(uint32_t dst, const void* src) {
    asm volatile("cp.async.cg.shared.global [%0], [%1], 16;" :: "r"(dst), "l"(src));
}
__device__ __forceinline__ uint32_t packh2(float a, float b) {
    uint32_t r;
    asm("{ .reg .f16 lo, hi; cvt.rn.f16.f32 lo, %1; cvt.rn.f16.f32 hi, %2; mov.b32 %0, {lo, hi}; }"
        : "=r"(r) : "f"(a), "f"(b));
    return r;
}
__device__ __forceinline__ void mma16(float* c, const uint4& a, const uint2& b) {
    asm("mma.sync.aligned.m16n8k16.row.col.f32.f16.f16.f32 "
        "{%0,%1,%2,%3}, {%4,%5,%6,%7}, {%8,%9}, {%0,%1,%2,%3};"
        : "+f"(c[0]), "+f"(c[1]), "+f"(c[2]), "+f"(c[3])
        : "r"(a.x), "r"(a.y), "r"(a.z), "r"(a.w), "r"(b.x), "r"(b.y));
}
__device__ __forceinline__ uint32_t fmap(float f) {
    uint32_t u = __float_as_uint(f);
    return (u >> 31) ? ~u : (u | 0x80000000u);
}
__device__ __forceinline__ float funmap(uint32_t u) {
    return __uint_as_float((u >> 31) ? (u & 0x7fffffffu) : ~u);
}

// ---------- prepass A: z -> fp16 plane (m16n8k16 A-frag order) + exact ||z||^2 ----------
// frag: a0=(g,2q+s) a1=(g+8,2q+s) a2=(g,8+2q+s) a3=(g+8,8+2q+s); g=lane>>2, q=lane&3
// f16 linear: t=(row>>4)*16+(d>>4); idx = t*256 + lane*8 + reg*2 + slot
__global__ void __launch_bounds__(256) prepA_kernel(const float* __restrict__ z) {
    __shared__ float zs[32 * 260];
    int tid = threadIdx.x;
    const float4* src = reinterpret_cast<const float4*>(z + (size_t)blockIdx.x * 32 * DIM);
    #pragma unroll
    for (int i = 0; i < 8; i++) {
        int gi = tid + i * 256;
        int row = gi >> 6, c4 = gi & 63;
        *reinterpret_cast<float4*>(&zs[row * 260 + c4 * 4]) = src[gi];
    }
    __syncthreads();
    uint4* outp = g_A4 + (size_t)blockIdx.x * 1024;
    #pragma unroll
    for (int i = 0; i < 4; i++) {
        int idx4 = tid + i * 256;            // uint4 id 0..1023
        int o = idx4 * 8;                    // f16 linear offset in block slice
        int t_local = o >> 8;                // 0..31
        int mt = t_local >> 4, kt = t_local & 15;
        int lane = (o >> 3) & 31;
        int g = lane >> 2, q = lane & 3;
        uint32_t w[4];
        #pragma unroll
        for (int reg = 0; reg < 4; reg++) {
            int row = mt * 16 + (reg & 1) * 8 + g;
            int col = kt * 16 + ((reg >> 1) & 1) * 8 + q * 2;
            w[reg] = packh2(zs[row * 260 + col], zs[row * 260 + col + 1]);
        }
        outp[idx4] = make_uint4(w[0], w[1], w[2], w[3]);
    }
    if (tid < 32) {   // exact sequential square-then-add (replicates reference)
        float s = 0.f;
        for (int d = 0; d < DIM; d++) {
            float v = zs[tid * 260 + d];
            s = __fadd_rn(s, __fmul_rn(v, v));
        }
        g_a[(size_t)blockIdx.x * 32 + tid] = s;
    }
}

// ---------- prepass B: e^T, ||e_k||^2, fp16 plane (B-frag order), hist zero ----------
// frag: b0=(2q+s, g) b1=(8+2q+s, g); u=(code>>3)*16+(d>>4); idx = u*128 + lane*4 + reg*2 + slot
__global__ void __launch_bounds__(256) prepB_kernel(const float* __restrict__ e) {
    int k = blockIdx.x;       // code 0..1023
    int d = threadIdx.x;      // dim  0..255
    float v = e[(size_t)d * K_CODES + k];
    g_eT[k * DIM + d] = v;

    __shared__ float red[256];
    red[d] = __fmul_rn(v, v);
    __syncthreads();
    #pragma unroll
    for (int off = 128; off > 0; off >>= 1) {
        if (d < off) red[d] = __fadd_rn(red[d], red[d + off]);
        __syncthreads();
    }
    if (d == 0) g_b[k] = red[0];
    if (blockIdx.x < 4) g_hist[blockIdx.x * 256 + d] = 0;

    int dk = d & 15;
    int q = (dk & 7) >> 1, reg = dk >> 3, slot = dk & 1;
    int lane = (k & 7) * 4 + q;
    int u = (k >> 3) * 16 + (d >> 4);
    unsigned short hb;
    asm("{ .reg .f16 h; cvt.rn.f16.f32 h, %1; mov.b16 %0, h; }" : "=h"(hb) : "f"(v));
    g_B16[u * 128 + lane * 4 + reg * 2 + slot] = hb;
}

// ---------- main filter GEMM (fp16 m16n8k16) + candidate shortlist + exact refine ----------
// CTA: 128 rows x all 1024 codes, 512 threads (16 warps = 4M x 4N), warp tile 32x32 per nb.
// smem u32: A[16384] | B 2st x 2048 @16384 | b_s[1024]@20480 | row_min[128]@21504 |
//           cnt[128]@21632 | cand[4096]@21760  -> 25856 u32 = 103424 B
#define SM_B    16384
#define SM_BS   20480
#define SM_RMIN 21504
#define SM_CNT  21632
#define SM_CAND 21760
#define GEMM_SMEM_BYTES (25856 * 4)

__global__ void __launch_bounds__(512) gemm_argmin_kernel(const float* __restrict__ z) {
    extern __shared__ __align__(16) float s[];
    uint32_t* s32 = reinterpret_cast<uint32_t*>(s);
    int tid = threadIdx.x, lane = tid & 31, wid = tid >> 5;
    int warp_m = wid & 3, warp_n = wid >> 2;
    int rblk = blockIdx.x;
    float* b_s = s + SM_BS;
    uint32_t* row_min = s32 + SM_RMIN;
    int* cnt = reinterpret_cast<int*>(s32 + SM_CNT);
    uint32_t* cand = s32 + SM_CAND;
    uint32_t sbase = smem_u32(s);

    // init scalars
    #pragma unroll
    for (int i = 0; i < 2; i++) b_s[tid + i * 512] = g_b[tid + i * 512];
    if (tid < 128) { row_min[tid] = 0xFFFFFFFFu; cnt[tid] = 0; }

    // A resident load: 4096 uint4 = 64KB, frag-linearized contiguous slice
    {
        const uint4* srcA = g_A4 + (size_t)rblk * 4096;
        #pragma unroll
        for (int i = 0; i < 8; i++) {
            int f = tid + i * 512;
            cp16(sbase + (uint32_t)f * 16, srcA + f);
        }
    }
    // B chunk loader: i -> (nb = i>>3, c = i&7); 512 uint4 = 8KB per chunk
    auto loadB = [&](int i) {
        int nb = i >> 3, c = i & 7, st = i & 1;
        int tile = tid >> 4, w = tid & 15;
        int nt = tile >> 1, ktl = tile & 1;
        const unsigned short* src = g_B16 + ((size_t)((nb * 16 + nt) * 16 + c * 2 + ktl)) * 128 + w * 8;
        cp16(sbase + (uint32_t)(SM_B + st * 2048 + tile * 64 + w * 4) * 4, src);
        asm volatile("cp.async.commit_group;" ::: "memory");
    };
    loadB(0);                                    // group 0 (includes A cp's)
    loadB(1);                                    // group 1

    float acc[2][4][4];
    int g = lane >> 2, q2 = (lane & 3) * 2;

    for (int i = 0; i < 64; i++) {
        int nb = i >> 3, c = i & 7, st = i & 1;
        if (i < 63) asm volatile("cp.async.wait_group 1;" ::: "memory");
        else        asm volatile("cp.async.wait_group 0;" ::: "memory");
        __syncthreads();

        if (c == 0) {
            #pragma unroll
            for (int m = 0; m < 2; m++)
                #pragma unroll
                for (int n = 0; n < 4; n++)
                    #pragma unroll
                    for (int j = 0; j < 4; j++) acc[m][n][j] = 0.f;
        }

        #pragma unroll
        for (int ktl = 0; ktl < 2; ktl++) {
            uint4 av[2];
            #pragma unroll
            for (int m = 0; m < 2; m++)
                av[m] = *reinterpret_cast<const uint4*>(
                    &s32[((warp_m * 2 + m) * 16 + c * 2 + ktl) * 128 + lane * 4]);
            uint2 bv[4];
            #pragma unroll
            for (int n = 0; n < 4; n++)
                bv[n] = *reinterpret_cast<const uint2*>(
                    &s32[SM_B + st * 2048 + ((warp_n * 4 + n) * 2 + ktl) * 64 + lane * 2]);
            #pragma unroll
            for (int m = 0; m < 2; m++)
                #pragma unroll
                for (int n = 0; n < 4; n++) mma16(acc[m][n], av[m], bv[n]);
        }

        if (c == 7) {
            // phase 1: per-row running min of selection metric d = b - 2m
            #pragma unroll
            for (int m = 0; m < 2; m++) {
                float mn0 = __int_as_float(0x7f800000), mn1 = mn0;
                #pragma unroll
                for (int n = 0; n < 4; n++) {
                    int nl = warp_n * 32 + n * 8 + q2;
                    float b0 = b_s[nb * 128 + nl], b1 = b_s[nb * 128 + nl + 1];
                    mn0 = fminf(mn0, fminf(__fmaf_rn(-2.f, acc[m][n][0], b0),
                                           __fmaf_rn(-2.f, acc[m][n][1], b1)));
                    mn1 = fminf(mn1, fminf(__fmaf_rn(-2.f, acc[m][n][2], b0),
                                           __fmaf_rn(-2.f, acc[m][n][3], b1)));
                }
                #pragma unroll
                for (int off = 1; off <= 2; off <<= 1) {
                    mn0 = fminf(mn0, __shfl_xor_sync(0xffffffffu, mn0, off));
                    mn1 = fminf(mn1, __shfl_xor_sync(0xffffffffu, mn1, off));
                }
                if ((lane & 3) == 0) {
                    int r0 = warp_m * 32 + m * 16 + g;
                    atomicMin(&row_min[r0], fmap(mn0));
                    atomicMin(&row_min[r0 + 8], fmap(mn1));
                }
            }
            __syncthreads();
            // phase 2: collect candidates within margin of running min
            #pragma unroll
            for (int m = 0; m < 2; m++) {
                int r0 = warp_m * 32 + m * 16 + g, r1 = r0 + 8;
                float t0 = funmap(row_min[r0]) + MARGIN;
                float t1 = funmap(row_min[r1]) + MARGIN;
                #pragma unroll
                for (int n = 0; n < 4; n++) {
                    int nl = warp_n * 32 + n * 8 + q2;
                    float b0 = b_s[nb * 128 + nl], b1 = b_s[nb * 128 + nl + 1];
                    unsigned code = (unsigned)(nb * 128 + nl);
                    float d00 = __fmaf_rn(-2.f, acc[m][n][0], b0);
                    float d01 = __fmaf_rn(-2.f, acc[m][n][1], b1);
                    float d10 = __fmaf_rn(-2.f, acc[m][n][2], b0);
                    float d11 = __fmaf_rn(-2.f, acc[m][n][3], b1);
                    if (d00 <= t0) { int p = atomicAdd(&cnt[r0], 1); if (p < 32) cand[r0 * 32 + p] = code; }
                    if (d01 <= t0) { int p = atomicAdd(&cnt[r0], 1); if (p < 32) cand[r0 * 32 + p] = code + 1; }
                    if (d10 <= t1) { int p = atomicAdd(&cnt[r1], 1); if (p < 32) cand[r1 * 32 + p] = code; }
                    if (d11 <= t1) { int p = atomicAdd(&cnt[r1], 1); if (p < 32) cand[r1 * 32 + p] = code + 1; }
                }
            }
        }
        __syncthreads();
        if (i + 2 < 64) loadB(i + 2);
    }

    // ---- exact refine: R2-identical numerics (sequential FMA, fl(fl(a+b)-2m)) ----
    if (tid < 128) {
        int row = rblk * 128 + tid;
        float a = g_a[row];
        int nc = cnt[tid]; if (nc > 32) nc = 32;
        const float* zr = z + (size_t)row * DIM;
        unsigned long long best = ~0ull;
        for (int ci = 0; ci < nc; ci++) {
            int k = (int)cand[tid * 32 + ci];
            const float* er = g_eT + (size_t)k * DIM;
            float m = 0.f;
            for (int d = 0; d < DIM; d++) m = __fmaf_rn(zr[d], er[d], m);
            float dist = __fsub_rn(__fadd_rn(a, b_s[k]), 2.0f * m);
            unsigned long long key =
                ((unsigned long long)__float_as_uint(dist) << 32) | (unsigned)k;
            if (key < best) best = key;
        }
        g_idx[row] = (int)(best & 0xFFFFFFFFull);
    }
}

// ---------------- gather + straight-through + loss partials + hist (float4) ----------------
__global__ void __launch_bounds__(256) gather_kernel(const float* __restrict__ z,
                                                     float* __restrict__ out_q,
                                                     float* __restrict__ out_if,
                                                     int write_q, int write_i) {
    int tid = threadIdx.x;
    int warp = tid >> 5, lane = tid & 31;
    size_t row = (size_t)blockIdx.x * 8 + warp;
    int k = g_idx[row];
    const float4* zr = reinterpret_cast<const float4*>(z + row * DIM);
    const float4* er = reinterpret_cast<const float4*>(g_eT + (size_t)k * DIM);
    float4* oq = reinterpret_cast<float4*>(out_q) + row * 64;

    float sq = 0.f;
    #pragma unroll
    for (int j = 0; j < 2; j++) {
        int i4 = lane + 32 * j;
        float4 zv = zr[i4];
        float4 qv = er[i4];
        float dx = __fsub_rn(qv.x, zv.x), dy = __fsub_rn(qv.y, zv.y);
        float dz = __fsub_rn(qv.z, zv.z), dw = __fsub_rn(qv.w, zv.w);
        if (write_q)
            oq[i4] = make_float4(__fadd_rn(zv.x, dx), __fadd_rn(zv.y, dy),
                                 __fadd_rn(zv.z, dz), __fadd_rn(zv.w, dw));
        sq = __fadd_rn(sq, __fmul_rn(dx, dx));
        sq = __fadd_rn(sq, __fmul_rn(dy, dy));
        sq = __fadd_rn(sq, __fmul_rn(dz, dz));
        sq = __fadd_rn(sq, __fmul_rn(dw, dw));
    }
    #pragma unroll
    for (int o = 16; o > 0; o >>= 1)
        sq = __fadd_rn(sq, __shfl_down_sync(0xffffffffu, sq, o));

    __shared__ float ws[8];
    if (lane == 0) {
        ws[warp] = sq;
        atomicAdd(&g_hist[k], 1);
        if (write_i) out_if[row] = (float)k;
    }
    __syncthreads();
    if (tid == 0) {
        float s = 0.f;
        #pragma unroll
        for (int w = 0; w < 8; w++) s = __fadd_rn(s, ws[w]);
        g_part[blockIdx.x] = s;
    }
}

// ---------------- final reductions ----------------
__global__ void __launch_bounds__(256) final_kernel(float* __restrict__ out_s, int write_s) {
    __shared__ float red[256];
    int tid = threadIdx.x;

    float s = 0.f;
    for (int i = tid; i < N_ROWS / 8; i += 256) s = __fadd_rn(s, g_part[i]);
    red[tid] = s;
    __syncthreads();
    #pragma unroll
    for (int off = 128; off > 0; off >>= 1) {
        if (tid < off) red[tid] = __fadd_rn(red[tid], red[tid + off]);
        __syncthreads();
    }
    float vq = red[0] / 16777216.0f;
    __syncthreads();

    float ps = 0.f;
    for (int i = tid; i < K_CODES; i += 256) {
        float p = (float)g_hist[i] * (1.0f / 65536.0f);
        ps = __fadd_rn(ps, __fmul_rn(p, logf(p + 1e-10f)));
    }
    red[tid] = ps;
    __syncthreads();
    #pragma unroll
    for (int off = 128; off > 0; off >>= 1) {
        if (tid < off) red[tid] = __fadd_rn(red[tid], red[tid + off]);
        __syncthreads();
    }
    if (tid == 0 && write_s) {
        out_s[0] = vq;
        out_s[1] = 0.25f * vq;
        out_s[2] = expf(-red[0]);
    }
}

// ---------------- launch ----------------
extern "C" void kernel_launch(void* const* d_in, const int* in_sizes, int n_in,
                              void* d_out, int out_size) {
    const float* z = (const float*)d_in[0];
    const float* e = (const float*)d_in[1];
    float* out = (float*)d_out;

    const int QN = N_ROWS * DIM;
    int write_q = (out_size >= QN) ? 1 : 0;
    int write_i = (out_size >= QN + N_ROWS) ? 1 : 0;
    int write_s = 0;
    float* out_q  = out;
    float* out_if = out + QN;
    float* out_s  = out;
    if (out_size >= QN + N_ROWS + 3) {
        write_s = 1; out_s = out + QN + N_ROWS;
    } else if (out_size == QN + 3) {
        write_s = 1; out_s = out + QN; write_i = 0;
    }

    cudaFuncSetAttribute(gemm_argmin_kernel,
                         cudaFuncAttributeMaxDynamicSharedMemorySize, GEMM_SMEM_BYTES);

    prepA_kernel<<<N_ROWS / 32, 256>>>(z);
    prepB_kernel<<<K_CODES, 256>>>(e);
    gemm_argmin_kernel<<<N_ROWS / 128, 512, GEMM_SMEM_BYTES>>>(z);
    gather_kernel<<<N_ROWS / 8, 256>>>(z, out_q, out_if, write_q, write_i);
    final_kernel<<<1, 256>>>(out_s, write_s);
}

// round 16
// speedup vs baseline: 1.8741x; 1.0031x over previous
#include <cuda_runtime.h>
#include <cstdint>

#define N_ROWS 65536
#define DIM    256
#define K_CODES 1024
#define MARGIN 2.5e-4f
#define NCAND  16

// ================= scratch (no allocations allowed) =================
__device__ uint4 g_A4[N_ROWS * 32];              // z fp16 plane, A-frag-linearized (8 f16/uint4)
__device__ unsigned short g_B16[K_CODES * DIM];  // e fp16 plane, B-frag-linearized
__device__ float g_eT[K_CODES * DIM];            // transposed codebook [k][d]
__device__ float g_a[N_ROWS];                    // ||z_row||^2 (exact replication)
__device__ float g_b[K_CODES];                   // ||e_k||^2
__device__ int   g_idx[N_ROWS];
__device__ int   g_hist[K_CODES];
__device__ float g_part[N_ROWS / 8];

// ================= helpers =================
__device__ __forceinline__ uint32_t smem_u32(const void* p) {
    uint32_t a;
    asm("{ .reg .u64 t; cvta.to.shared.u64 t, %1; cvt.u32.u64 %0, t; }" : "=r"(a) : "l"(p));
    return a;
}
__device__ __forceinline__ void cp16(uint32_t dst, const void* src) {
    asm volatile("cp.async.cg.shared.global [%0], [%1], 16;" :: "r"(dst), "l"(src));
}
__device__ __forceinline__ uint32_t packh2(float a, float b) {
    uint32_t r;
    asm("{ .reg .f16 lo, hi; cvt.rn.f16.f32 lo, %1; cvt.rn.f16.f32 hi, %2; mov.b32 %0, {lo, hi}; }"
        : "=r"(r) : "f"(a), "f"(b));
    return r;
}
__device__ __forceinline__ void mma16(float* c, const uint4& a, const uint2& b) {
    asm("mma.sync.aligned.m16n8k16.row.col.f32.f16.f16.f32 "
        "{%0,%1,%2,%3}, {%4,%5,%6,%7}, {%8,%9}, {%0,%1,%2,%3};"
        : "+f"(c[0]), "+f"(c[1]), "+f"(c[2]), "+f"(c[3])
        : "r"(a.x), "r"(a.y), "r"(a.z), "r"(a.w), "r"(b.x), "r"(b.y));
}
__device__ __forceinline__ uint32_t fmap(float f) {
    uint32_t u = __float_as_uint(f);
    return (u >> 31) ? ~u : (u | 0x80000000u);
}
__device__ __forceinline__ float funmap(uint32_t u) {
    return __uint_as_float((u >> 31) ? (u & 0x7fffffffu) : ~u);
}

// ---------- prepass A: z -> fp16 plane (m16n8k16 A-frag order) + exact ||z||^2 ----------
// frag: a0=(g,2q+s) a1=(g+8,2q+s) a2=(g,8+2q+s) a3=(g+8,8+2q+s); g=lane>>2, q=lane&3
// f16 linear: t=(row>>4)*16+(d>>4); idx = t*256 + lane*8 + reg*2 + slot
__global__ void __launch_bounds__(256) prepA_kernel(const float* __restrict__ z) {
    __shared__ float zs[32 * 260];
    int tid = threadIdx.x;
    const float4* src = reinterpret_cast<const float4*>(z + (size_t)blockIdx.x * 32 * DIM);
    #pragma unroll
    for (int i = 0; i < 8; i++) {
        int gi = tid + i * 256;
        int row = gi >> 6, c4 = gi & 63;
        *reinterpret_cast<float4*>(&zs[row * 260 + c4 * 4]) = src[gi];
    }
    __syncthreads();
    uint4* outp = g_A4 + (size_t)blockIdx.x * 1024;
    #pragma unroll
    for (int i = 0; i < 4; i++) {
        int idx4 = tid + i * 256;            // uint4 id 0..1023
        int o = idx4 * 8;                    // f16 linear offset in block slice
        int t_local = o >> 8;                // 0..31
        int mt = t_local >> 4, kt = t_local & 15;
        int lane = (o >> 3) & 31;
        int g = lane >> 2, q = lane & 3;
        uint32_t w[4];
        #pragma unroll
        for (int reg = 0; reg < 4; reg++) {
            int row = mt * 16 + (reg & 1) * 8 + g;
            int col = kt * 16 + ((reg >> 1) & 1) * 8 + q * 2;
            w[reg] = packh2(zs[row * 260 + col], zs[row * 260 + col + 1]);
        }
        outp[idx4] = make_uint4(w[0], w[1], w[2], w[3]);
    }
    if (tid < 32) {   // exact sequential square-then-add (replicates reference)
        float s = 0.f;
        for (int d = 0; d < DIM; d++) {
            float v = zs[tid * 260 + d];
            s = __fadd_rn(s, __fmul_rn(v, v));
        }
        g_a[(size_t)blockIdx.x * 32 + tid] = s;
    }
}

// ---------- prepass B: e^T, ||e_k||^2, fp16 plane (B-frag order), hist zero ----------
// frag: b0=(2q+s, g) b1=(8+2q+s, g); u=(code>>3)*16+(d>>4); idx = u*128 + lane*4 + reg*2 + slot
__global__ void __launch_bounds__(256) prepB_kernel(const float* __restrict__ e) {
    int k = blockIdx.x;       // code 0..1023
    int d = threadIdx.x;      // dim  0..255
    float v = e[(size_t)d * K_CODES + k];
    g_eT[k * DIM + d] = v;

    __shared__ float red[256];
    red[d] = __fmul_rn(v, v);
    __syncthreads();
    #pragma unroll
    for (int off = 128; off > 0; off >>= 1) {
        if (d < off) red[d] = __fadd_rn(red[d], red[d + off]);
        __syncthreads();
    }
    if (d == 0) g_b[k] = red[0];
    if (blockIdx.x < 4) g_hist[blockIdx.x * 256 + d] = 0;

    int dk = d & 15;
    int q = (dk & 7) >> 1, reg = dk >> 3, slot = dk & 1;
    int lane = (k & 7) * 4 + q;
    int u = (k >> 3) * 16 + (d >> 4);
    unsigned short hb;
    asm("{ .reg .f16 h; cvt.rn.f16.f32 h, %1; mov.b16 %0, h; }" : "=h"(hb) : "f"(v));
    g_B16[u * 128 + lane * 4 + reg * 2 + slot] = hb;
}

// ---------- main filter GEMM (fp16 m16n8k16, block-resident-K) + shortlist + refine ----------
// CTA: 128 rows x all 1024 codes, 512 threads = 16 warps (4m x 4n), warp tile 32x32 per block.
// 8 pipeline iterations; each = one 128-code block with FULL K=256 (16 kt, 128 HMMA/warp).
// smem u32: A[16384]@0 | B 2st x 16384 @16384 | b_s[1024]@49152 | row_min[128]@50176 |
//           cnt[128]@50304 | cand[2048]@50432  -> 52480 u32 = 209920 B
#define SM_B    16384
#define SM_BS   49152
#define SM_RMIN 50176
#define SM_CNT  50304
#define SM_CAND 50432
#define GEMM_SMEM_BYTES (52480 * 4)

__global__ void __launch_bounds__(512, 1) gemm_argmin_kernel(const float* __restrict__ z) {
    extern __shared__ __align__(16) uint32_t s32[];
    int tid = threadIdx.x, lane = tid & 31, wid = tid >> 5;
    int warp_m = wid & 3, warp_n = wid >> 2;
    int rblk = blockIdx.x;
    float* b_s = reinterpret_cast<float*>(s32 + SM_BS);
    uint32_t* row_min = s32 + SM_RMIN;
    int* cnt = reinterpret_cast<int*>(s32 + SM_CNT);
    uint32_t* cand = s32 + SM_CAND;
    uint32_t sbase = smem_u32(s32);

    #pragma unroll
    for (int i = 0; i < 2; i++) b_s[tid + i * 512] = g_b[tid + i * 512];
    if (tid < 128) { row_min[tid] = 0xFFFFFFFFu; cnt[tid] = 0; }

    // A resident: 4096 uint4 = 64KB, frag-linearized contiguous slice
    {
        const uint4* srcA = g_A4 + (size_t)rblk * 4096;
        #pragma unroll
        for (int i = 0; i < 8; i++) {
            int f = tid + i * 512;
            cp16(sbase + (uint32_t)f * 16, srcA + f);
        }
    }
    // B chunk = one 128-code block, full K=256: 4096 uint4 = 64KB, contiguous in g_B16
    auto loadB = [&](int i) {
        int st = i & 1;
        const uint4* srcB = reinterpret_cast<const uint4*>(g_B16) + (size_t)i * 4096;
        #pragma unroll
        for (int it = 0; it < 8; it++) {
            int f = tid + it * 512;
            cp16(sbase + (uint32_t)(SM_B + st * 16384) * 4 + (uint32_t)f * 16, srcB + f);
        }
        asm volatile("cp.async.commit_group;" ::: "memory");
    };
    loadB(0);    // group 0 (includes A)
    loadB(1);    // group 1

    int g = lane >> 2, q2 = (lane & 3) * 2;
    int rowbase = rblk * 128;
    float acc[2][4][4];

    for (int nb = 0; nb < 8; nb++) {
        if (nb < 7) asm volatile("cp.async.wait_group 1;" ::: "memory");
        else        asm volatile("cp.async.wait_group 0;" ::: "memory");
        __syncthreads();

        #pragma unroll
        for (int m = 0; m < 2; m++)
            #pragma unroll
            for (int n = 0; n < 4; n++)
                #pragma unroll
                for (int j = 0; j < 4; j++) acc[m][n][j] = 0.f;

        const uint32_t* Bs = s32 + SM_B + (nb & 1) * 16384;
        #pragma unroll
        for (int kt = 0; kt < 16; kt++) {
            uint4 av[2];
            #pragma unroll
            for (int m = 0; m < 2; m++)
                av[m] = *reinterpret_cast<const uint4*>(
                    &s32[((warp_m * 2 + m) * 16 + kt) * 128 + lane * 4]);
            uint2 bv[4];
            #pragma unroll
            for (int n = 0; n < 4; n++)
                bv[n] = *reinterpret_cast<const uint2*>(
                    &Bs[((warp_n * 4 + n) * 16 + kt) * 64 + lane * 2]);
            #pragma unroll
            for (int m = 0; m < 2; m++)
                #pragma unroll
                for (int n = 0; n < 4; n++) mma16(acc[m][n], av[m], bv[n]);
        }

        // phase 1: per-row running min of selection metric d = b - 2m
        #pragma unroll
        for (int m = 0; m < 2; m++) {
            float mn0 = __int_as_float(0x7f800000), mn1 = mn0;
            #pragma unroll
            for (int n = 0; n < 4; n++) {
                int nl = warp_n * 32 + n * 8 + q2;
                float b0 = b_s[nb * 128 + nl], b1 = b_s[nb * 128 + nl + 1];
                mn0 = fminf(mn0, fminf(__fmaf_rn(-2.f, acc[m][n][0], b0),
                                       __fmaf_rn(-2.f, acc[m][n][1], b1)));
                mn1 = fminf(mn1, fminf(__fmaf_rn(-2.f, acc[m][n][2], b0),
                                       __fmaf_rn(-2.f, acc[m][n][3], b1)));
            }
            #pragma unroll
            for (int off = 1; off <= 2; off <<= 1) {
                mn0 = fminf(mn0, __shfl_xor_sync(0xffffffffu, mn0, off));
                mn1 = fminf(mn1, __shfl_xor_sync(0xffffffffu, mn1, off));
            }
            if ((lane & 3) == 0) {
                int r0 = warp_m * 32 + m * 16 + g;
                atomicMin(&row_min[r0], fmap(mn0));
                atomicMin(&row_min[r0 + 8], fmap(mn1));
            }
        }
        __syncthreads();
        if (nb < 6) loadB(nb + 2);   // stage nb&1 fully consumed (reads done before sync)

        // phase 2: collect candidates within margin of running min (registers only)
        #pragma unroll
        for (int m = 0; m < 2; m++) {
            int r0 = warp_m * 32 + m * 16 + g, r1 = r0 + 8;
            float t0 = funmap(row_min[r0]) + MARGIN;
            float t1 = funmap(row_min[r1]) + MARGIN;
            #pragma unroll
            for (int n = 0; n < 4; n++) {
                int nl = warp_n * 32 + n * 8 + q2;
                float b0 = b_s[nb * 128 + nl], b1 = b_s[nb * 128 + nl + 1];
                unsigned code = (unsigned)(nb * 128 + nl);
                float d00 = __fmaf_rn(-2.f, acc[m][n][0], b0);
                float d01 = __fmaf_rn(-2.f, acc[m][n][1], b1);
                float d10 = __fmaf_rn(-2.f, acc[m][n][2], b0);
                float d11 = __fmaf_rn(-2.f, acc[m][n][3], b1);
                if (d00 <= t0) { int p = atomicAdd(&cnt[r0], 1); if (p < NCAND) cand[r0 * NCAND + p] = code; }
                if (d01 <= t0) { int p = atomicAdd(&cnt[r0], 1); if (p < NCAND) cand[r0 * NCAND + p] = code + 1; }
                if (d10 <= t1) { int p = atomicAdd(&cnt[r1], 1); if (p < NCAND) cand[r1 * NCAND + p] = code; }
                if (d11 <= t1) { int p = atomicAdd(&cnt[r1], 1); if (p < NCAND) cand[r1 * NCAND + p] = code + 1; }
            }
        }
    }
    __syncthreads();

    // ---- exact refine: R2-identical numerics (sequential FMA, fl(fl(a+b)-2m)) ----
    if (tid < 128) {
        int row = rowbase + tid;
        float a = g_a[row];
        int nc = cnt[tid]; if (nc > NCAND) nc = NCAND;
        const float* zr = z + (size_t)row * DIM;
        unsigned long long best = ~0ull;
        for (int ci = 0; ci < nc; ci++) {
            int k = (int)cand[tid * NCAND + ci];
            const float* er = g_eT + (size_t)k * DIM;
            float m = 0.f;
            for (int d = 0; d < DIM; d++) m = __fmaf_rn(zr[d], er[d], m);
            float dist = __fsub_rn(__fadd_rn(a, b_s[k]), 2.0f * m);
            unsigned long long key =
                ((unsigned long long)__float_as_uint(dist) << 32) | (unsigned)k;
            if (key < best) best = key;
        }
        g_idx[row] = (int)(best & 0xFFFFFFFFull);
    }
}

// ---------------- gather + straight-through + loss partials + hist (float4) ----------------
__global__ void __launch_bounds__(256) gather_kernel(const float* __restrict__ z,
                                                     float* __restrict__ out_q,
                                                     float* __restrict__ out_if,
                                                     int write_q, int write_i) {
    int tid = threadIdx.x;
    int warp = tid >> 5, lane = tid & 31;
    size_t row = (size_t)blockIdx.x * 8 + warp;
    int k = g_idx[row];
    const float4* zr = reinterpret_cast<const float4*>(z + row * DIM);
    const float4* er = reinterpret_cast<const float4*>(g_eT + (size_t)k * DIM);
    float4* oq = reinterpret_cast<float4*>(out_q) + row * 64;

    float sq = 0.f;
    #pragma unroll
    for (int j = 0; j < 2; j++) {
        int i4 = lane + 32 * j;
        float4 zv = zr[i4];
        float4 qv = er[i4];
        float dx = __fsub_rn(qv.x, zv.x), dy = __fsub_rn(qv.y, zv.y);
        float dz = __fsub_rn(qv.z, zv.z), dw = __fsub_rn(qv.w, zv.w);
        if (write_q)
            oq[i4] = make_float4(__fadd_rn(zv.x, dx), __fadd_rn(zv.y, dy),
                                 __fadd_rn(zv.z, dz), __fadd_rn(zv.w, dw));
        sq = __fadd_rn(sq, __fmul_rn(dx, dx));
        sq = __fadd_rn(sq, __fmul_rn(dy, dy));
        sq = __fadd_rn(sq, __fmul_rn(dz, dz));
        sq = __fadd_rn(sq, __fmul_rn(dw, dw));
    }
    #pragma unroll
    for (int o = 16; o > 0; o >>= 1)
        sq = __fadd_rn(sq, __shfl_down_sync(0xffffffffu, sq, o));

    __shared__ float ws[8];
    if (lane == 0) {
        ws[warp] = sq;
        atomicAdd(&g_hist[k], 1);
        if (write_i) out_if[row] = (float)k;
    }
    __syncthreads();
    if (tid == 0) {
        float s = 0.f;
        #pragma unroll
        for (int w = 0; w < 8; w++) s = __fadd_rn(s, ws[w]);
        g_part[blockIdx.x] = s;
    }
}

// ---------------- final reductions ----------------
__global__ void __launch_bounds__(256) final_kernel(float* __restrict__ out_s, int write_s) {
    __shared__ float red[256];
    int tid = threadIdx.x;

    float s = 0.f;
    for (int i = tid; i < N_ROWS / 8; i += 256) s = __fadd_rn(s, g_part[i]);
    red[tid] = s;
    __syncthreads();
    #pragma unroll
    for (int off = 128; off > 0; off >>= 1) {
        if (tid < off) red[tid] = __fadd_rn(red[tid], red[tid + off]);
        __syncthreads();
    }
    float vq = red[0] / 16777216.0f;
    __syncthreads();

    float ps = 0.f;
    for (int i = tid; i < K_CODES; i += 256) {
        float p = (float)g_hist[i] * (1.0f / 65536.0f);
        ps = __fadd_rn(ps, __fmul_rn(p, logf(p + 1e-10f)));
    }
    red[tid] = ps;
    __syncthreads();
    #pragma unroll
    for (int off = 128; off > 0; off >>= 1) {
        if (tid < off) red[tid] = __fadd_rn(red[tid], red[tid + off]);
        __syncthreads();
    }
    if (tid == 0 && write_s) {
        out_s[0] = vq;
        out_s[1] = 0.25f * vq;
        out_s[2] = expf(-red[0]);
    }
}

// ---------------- launch ----------------
extern "C" void kernel_launch(void* const* d_in, const int* in_sizes, int n_in,
                              void* d_out, int out_size) {
    const float* z = (const float*)d_in[0];
    const float* e = (const float*)d_in[1];
    float* out = (float*)d_out;

    const int QN = N_ROWS * DIM;
    int write_q = (out_size >= QN) ? 1 : 0;
    int write_i = (out_size >= QN + N_ROWS) ? 1 : 0;
    int write_s = 0;
    float* out_q  = out;
    float* out_if = out + QN;
    float* out_s  = out;
    if (out_size >= QN + N_ROWS + 3) {
        write_s = 1; out_s = out + QN + N_ROWS;
    } else if (out_size == QN + 3) {
        write_s = 1; out_s = out + QN; write_i = 0;
    }

    cudaFuncSetAttribute(gemm_argmin_kernel,
                         cudaFuncAttributeMaxDynamicSharedMemorySize, GEMM_SMEM_BYTES);

    prepA_kernel<<<N_ROWS / 32, 256>>>(z);
    prepB_kernel<<<K_CODES, 256>>>(e);
    gemm_argmin_kernel<<<N_ROWS / 128, 512, GEMM_SMEM_BYTES>>>(z);
    gather_kernel<<<N_ROWS / 8, 256>>>(z, out_q, out_if, write_q, write_i);
    final_kernel<<<1, 256>>>(out_s, write_s);
}